// round 4
// baseline (speedup 1.0000x reference)
#include <cuda_runtime.h>
#include <math.h>

#define TT   4096      // tokens
#define DD   1024      // model dim
#define HH   512       // expert hidden
#define EE   32        // experts
#define KTOP 4
#define CAP  2048      // capacity per expert
#define HS   1024      // shared hidden

// ---------------- scratch (device globals; no allocations allowed) ----------
__device__ int   g_cnt[EE];
__device__ int   g_pid[EE * CAP];            // pair id = tok*4 + k
__device__ float g_wt [EE * CAP];            // gate weight per pair
__device__ float g_h  [(size_t)EE * CAP * HH]; // routed hidden (silu(a)*b)
__device__ float g_hs [(size_t)TT * HS];       // shared hidden
__device__ float g_po [(size_t)TT * KTOP * DD];// per-pair FFN output

// ---------------------------------------------------------------------------
__global__ void zero_cnt_kernel() {
    if (threadIdx.x < EE) g_cnt[threadIdx.x] = 0;
}

// one block (128 thr) per token: logits -> softmax -> top4 -> dispatch
__global__ void gate_kernel(const float* __restrict__ x,
                            const float* __restrict__ Wg) {
    __shared__ float xs[DD];
    __shared__ float part[4][EE];
    int t = blockIdx.x;
    const float* xr = x + (size_t)t * DD;
    for (int i = threadIdx.x; i < DD / 4; i += 128)
        ((float4*)xs)[i] = ((const float4*)xr)[i];
    __syncthreads();

    int e = threadIdx.x & 31;
    int c = threadIdx.x >> 5;          // chunk 0..3
    float s = 0.f;
    int d0 = c * (DD / 4);
    for (int d = d0; d < d0 + DD / 4; d++)
        s += xs[d] * Wg[d * EE + e];
    part[c][e] = s;
    __syncthreads();

    if (threadIdx.x < 32) {
        float logit = part[0][e] + part[1][e] + part[2][e] + part[3][e];
        float m = logit;
        for (int o = 16; o; o >>= 1) m = fmaxf(m, __shfl_xor_sync(~0u, m, o));
        float ex = expf(logit - m);
        float sum = ex;
        for (int o = 16; o; o >>= 1) sum += __shfl_xor_sync(~0u, sum, o);
        float score = ex / sum;

        float v = score;
        for (int k = 0; k < KTOP; k++) {
            float bv = v; int bi = e;
            for (int o = 16; o; o >>= 1) {
                float ov = __shfl_xor_sync(~0u, bv, o);
                int   oi = __shfl_xor_sync(~0u, bi, o);
                if (ov > bv || (ov == bv && oi < bi)) { bv = ov; bi = oi; }
            }
            if (e == 0) {
                int slot = atomicAdd(&g_cnt[bi], 1);
                if (slot < CAP) {
                    g_pid[bi * CAP + slot] = t * KTOP + k;
                    g_wt [bi * CAP + slot] = bv;
                }
            }
            if (e == bi) v = -1.0f;    // knock out (scores are in (0,1))
        }
    }
}

__device__ __forceinline__ float silu_f(float a) {
    return a / (1.0f + expf(-a));
}

// routed GEMM1: h = silu(xg @ W1[e]) * (xg @ W3[e]); grid (H/64, CAP/64, E)
__global__ void __launch_bounds__(256)
moe_ffn1_kernel(const float* __restrict__ x,
                const float* __restrict__ W1,
                const float* __restrict__ W3) {
    int e  = blockIdx.z;
    int n0 = blockIdx.x * 64;
    int m0 = blockIdx.y * 64;
    int cnt = g_cnt[e]; if (cnt > CAP) cnt = CAP;
    if (m0 >= cnt) return;

    __shared__ float As [16][64];
    __shared__ float B1s[16][64];
    __shared__ float B3s[16][64];
    __shared__ int   rows[64];

    int tid = threadIdx.x;
    if (tid < 64) {
        int r = m0 + tid;
        rows[tid] = (r < cnt) ? (g_pid[e * CAP + r] >> 2) : -1;
    }
    __syncthreads();

    const float* W1e = W1 + (size_t)e * DD * HH;
    const float* W3e = W3 + (size_t)e * DD * HH;

    float acc1[4][4] = {}, acc3[4][4] = {};
    int ty = tid >> 4, tx = tid & 15;
    int lr = tid >> 2, lk4 = tid & 3;      // A-tile load coords
    int bk = tid >> 4, bn4 = tid & 15;     // B-tile load coords

    for (int k0 = 0; k0 < DD; k0 += 16) {
        float4 av = make_float4(0.f, 0.f, 0.f, 0.f);
        int tok = rows[lr];
        if (tok >= 0)
            av = *(const float4*)(x + (size_t)tok * DD + k0 + lk4 * 4);
        As[lk4 * 4 + 0][lr] = av.x; As[lk4 * 4 + 1][lr] = av.y;
        As[lk4 * 4 + 2][lr] = av.z; As[lk4 * 4 + 3][lr] = av.w;

        *(float4*)&B1s[bk][bn4 * 4] =
            *(const float4*)(W1e + (size_t)(k0 + bk) * HH + n0 + bn4 * 4);
        *(float4*)&B3s[bk][bn4 * 4] =
            *(const float4*)(W3e + (size_t)(k0 + bk) * HH + n0 + bn4 * 4);
        __syncthreads();

#pragma unroll
        for (int kk = 0; kk < 16; kk++) {
            float a[4], b1r[4], b3r[4];
            *(float4*)a   = *(float4*)&As [kk][ty * 4];
            *(float4*)b1r = *(float4*)&B1s[kk][tx * 4];
            *(float4*)b3r = *(float4*)&B3s[kk][tx * 4];
#pragma unroll
            for (int i = 0; i < 4; i++)
#pragma unroll
                for (int j = 0; j < 4; j++) {
                    acc1[i][j] += a[i] * b1r[j];
                    acc3[i][j] += a[i] * b3r[j];
                }
        }
        __syncthreads();
    }

#pragma unroll
    for (int i = 0; i < 4; i++) {
        int r = m0 + ty * 4 + i;
        if (r >= cnt) continue;
        float* hp = g_h + ((size_t)e * CAP + r) * HH + n0 + tx * 4;
        float4 o;
        o.x = silu_f(acc1[i][0]) * acc3[i][0];
        o.y = silu_f(acc1[i][1]) * acc3[i][1];
        o.z = silu_f(acc1[i][2]) * acc3[i][2];
        o.w = silu_f(acc1[i][3]) * acc3[i][3];
        *(float4*)hp = o;
    }
}

// routed GEMM2: po[pid] = (h @ W2[e]) * w; grid (D/64, CAP/64, E)
__global__ void __launch_bounds__(256)
moe_ffn2_kernel(const float* __restrict__ W2) {
    int e  = blockIdx.z;
    int n0 = blockIdx.x * 64;
    int m0 = blockIdx.y * 64;
    int cnt = g_cnt[e]; if (cnt > CAP) cnt = CAP;
    if (m0 >= cnt) return;

    __shared__ float As[16][64];
    __shared__ float Bs[16][64];

    int tid = threadIdx.x;
    const float* W2e = W2 + (size_t)e * HH * DD;

    float acc[4][4] = {};
    int ty = tid >> 4, tx = tid & 15;
    int lr = tid >> 2, lk4 = tid & 3;
    int bk = tid >> 4, bn4 = tid & 15;

    for (int k0 = 0; k0 < HH; k0 += 16) {
        float4 av = make_float4(0.f, 0.f, 0.f, 0.f);
        int r = m0 + lr;
        if (r < cnt)
            av = *(const float4*)(g_h + ((size_t)e * CAP + r) * HH + k0 + lk4 * 4);
        As[lk4 * 4 + 0][lr] = av.x; As[lk4 * 4 + 1][lr] = av.y;
        As[lk4 * 4 + 2][lr] = av.z; As[lk4 * 4 + 3][lr] = av.w;

        *(float4*)&Bs[bk][bn4 * 4] =
            *(const float4*)(W2e + (size_t)(k0 + bk) * DD + n0 + bn4 * 4);
        __syncthreads();

#pragma unroll
        for (int kk = 0; kk < 16; kk++) {
            float a[4], br[4];
            *(float4*)a  = *(float4*)&As[kk][ty * 4];
            *(float4*)br = *(float4*)&Bs[kk][tx * 4];
#pragma unroll
            for (int i = 0; i < 4; i++)
#pragma unroll
                for (int j = 0; j < 4; j++)
                    acc[i][j] += a[i] * br[j];
        }
        __syncthreads();
    }

#pragma unroll
    for (int i = 0; i < 4; i++) {
        int r = m0 + ty * 4 + i;
        if (r >= cnt) continue;
        int   pid = g_pid[e * CAP + r];
        float w   = g_wt [e * CAP + r];
        float* op = g_po + (size_t)pid * DD + n0 + tx * 4;
        float4 o;
        o.x = acc[i][0] * w; o.y = acc[i][1] * w;
        o.z = acc[i][2] * w; o.w = acc[i][3] * w;
        *(float4*)op = o;
    }
}

// shared GEMM1: hs = silu(x @ Ws1) * (x @ Ws3); grid (HS/64, T/64)
__global__ void __launch_bounds__(256)
shared_ffn1_kernel(const float* __restrict__ x,
                   const float* __restrict__ Ws1,
                   const float* __restrict__ Ws3) {
    int n0 = blockIdx.x * 64;
    int m0 = blockIdx.y * 64;

    __shared__ float As [16][64];
    __shared__ float B1s[16][64];
    __shared__ float B3s[16][64];

    int tid = threadIdx.x;
    float acc1[4][4] = {}, acc3[4][4] = {};
    int ty = tid >> 4, tx = tid & 15;
    int lr = tid >> 2, lk4 = tid & 3;
    int bk = tid >> 4, bn4 = tid & 15;

    for (int k0 = 0; k0 < DD; k0 += 16) {
        float4 av = *(const float4*)(x + (size_t)(m0 + lr) * DD + k0 + lk4 * 4);
        As[lk4 * 4 + 0][lr] = av.x; As[lk4 * 4 + 1][lr] = av.y;
        As[lk4 * 4 + 2][lr] = av.z; As[lk4 * 4 + 3][lr] = av.w;

        *(float4*)&B1s[bk][bn4 * 4] =
            *(const float4*)(Ws1 + (size_t)(k0 + bk) * HS + n0 + bn4 * 4);
        *(float4*)&B3s[bk][bn4 * 4] =
            *(const float4*)(Ws3 + (size_t)(k0 + bk) * HS + n0 + bn4 * 4);
        __syncthreads();

#pragma unroll
        for (int kk = 0; kk < 16; kk++) {
            float a[4], b1r[4], b3r[4];
            *(float4*)a   = *(float4*)&As [kk][ty * 4];
            *(float4*)b1r = *(float4*)&B1s[kk][tx * 4];
            *(float4*)b3r = *(float4*)&B3s[kk][tx * 4];
#pragma unroll
            for (int i = 0; i < 4; i++)
#pragma unroll
                for (int j = 0; j < 4; j++) {
                    acc1[i][j] += a[i] * b1r[j];
                    acc3[i][j] += a[i] * b3r[j];
                }
        }
        __syncthreads();
    }

#pragma unroll
    for (int i = 0; i < 4; i++) {
        int r = m0 + ty * 4 + i;
        float* hp = g_hs + (size_t)r * HS + n0 + tx * 4;
        float4 o;
        o.x = silu_f(acc1[i][0]) * acc3[i][0];
        o.y = silu_f(acc1[i][1]) * acc3[i][1];
        o.z = silu_f(acc1[i][2]) * acc3[i][2];
        o.w = silu_f(acc1[i][3]) * acc3[i][3];
        *(float4*)hp = o;
    }
}

// shared GEMM2: y = hs @ Ws2 (plain store); grid (D/64, T/64)
__global__ void __launch_bounds__(256)
shared_ffn2_kernel(const float* __restrict__ Ws2, float* __restrict__ y) {
    int n0 = blockIdx.x * 64;
    int m0 = blockIdx.y * 64;

    __shared__ float As[16][64];
    __shared__ float Bs[16][64];

    int tid = threadIdx.x;
    float acc[4][4] = {};
    int ty = tid >> 4, tx = tid & 15;
    int lr = tid >> 2, lk4 = tid & 3;
    int bk = tid >> 4, bn4 = tid & 15;

    for (int k0 = 0; k0 < HS; k0 += 16) {
        float4 av = *(const float4*)(g_hs + (size_t)(m0 + lr) * HS + k0 + lk4 * 4);
        As[lk4 * 4 + 0][lr] = av.x; As[lk4 * 4 + 1][lr] = av.y;
        As[lk4 * 4 + 2][lr] = av.z; As[lk4 * 4 + 3][lr] = av.w;

        *(float4*)&Bs[bk][bn4 * 4] =
            *(const float4*)(Ws2 + (size_t)(k0 + bk) * DD + n0 + bn4 * 4);
        __syncthreads();

#pragma unroll
        for (int kk = 0; kk < 16; kk++) {
            float a[4], br[4];
            *(float4*)a  = *(float4*)&As[kk][ty * 4];
            *(float4*)br = *(float4*)&Bs[kk][tx * 4];
#pragma unroll
            for (int i = 0; i < 4; i++)
#pragma unroll
                for (int j = 0; j < 4; j++)
                    acc[i][j] += a[i] * br[j];
        }
        __syncthreads();
    }

#pragma unroll
    for (int i = 0; i < 4; i++) {
        int r = m0 + ty * 4 + i;
        float* op = y + (size_t)r * DD + n0 + tx * 4;
        float4 o;
        o.x = acc[i][0]; o.y = acc[i][1]; o.z = acc[i][2]; o.w = acc[i][3];
        *(float4*)op = o;
    }
}

// combine: y[t] += sum_k po[t*4+k]
__global__ void combine_kernel(float* __restrict__ y) {
    size_t i  = (size_t)blockIdx.x * 256 + threadIdx.x;   // float4 index
    size_t t  = i >> 8;            // D/4 = 256 f4 per token
    size_t c4 = i & 255;
    float4 acc = ((float4*)y)[i];
    const float4* po4 = (const float4*)g_po;
#pragma unroll
    for (int k = 0; k < KTOP; k++) {
        float4 p = po4[(t * KTOP + k) * (DD / 4) + c4];
        acc.x += p.x; acc.y += p.y; acc.z += p.z; acc.w += p.w;
    }
    ((float4*)y)[i] = acc;
}

// ---------------------------------------------------------------------------
extern "C" void kernel_launch(void* const* d_in, const int* in_sizes, int n_in,
                              void* d_out, int out_size) {
    const float* x   = (const float*)d_in[0];
    const float* Wg  = (const float*)d_in[1];
    const float* W1  = (const float*)d_in[2];
    const float* W2  = (const float*)d_in[3];
    const float* W3  = (const float*)d_in[4];
    const float* Ws1 = (const float*)d_in[5];
    const float* Ws2 = (const float*)d_in[6];
    const float* Ws3 = (const float*)d_in[7];
    float* y = (float*)d_out;

    zero_cnt_kernel<<<1, 32>>>();
    gate_kernel<<<TT, 128>>>(x, Wg);
    moe_ffn1_kernel<<<dim3(HH / 64, CAP / 64, EE), 256>>>(x, W1, W3);
    shared_ffn1_kernel<<<dim3(HS / 64, TT / 64), 256>>>(x, Ws1, Ws3);
    shared_ffn2_kernel<<<dim3(DD / 64, TT / 64), 256>>>(Ws2, y);
    moe_ffn2_kernel<<<dim3(DD / 64, CAP / 64, EE), 256>>>(W2);
    combine_kernel<<<(TT * DD) / 1024, 256>>>(y);
}